// round 13
// baseline (speedup 1.0000x reference)
#include <cuda_runtime.h>
#include <cstdint>

#define BATCH 2
#define NPTS 8192
#define IMGS 64
#define KSEL 8
#define RAD2 0.0025f
#define RADM 0.0501f            // conservative bbox radius
#define NPIX (BATCH * IMGS * IMGS)   // 8192
#define CAP 256                 // per-pixel capacity (hot pixel ~150; +13 sigma)
#define OUTN (3 * NPIX * KSEL)  // 196608 floats

// Static scratch (allocation-free). BSS-zero at load; select_k restores
// g_cnt to zero every launch (graph-replay invariant).
__device__ int g_cnt[NPIX];
__device__ ulonglong2 g_plist[(size_t)NPIX * CAP];   // {key, d2bits} — 32 MB

// ---------------------------------------------------------------------------
// Kernel A: -1-fill the output, then project + scatter. EIGHT lanes per
// point, each owns a 1x2 sub-row of the 4x4 bbox. Ends in
// griddepcontrol.launch_dependents (PDL) so select_k releases early.
// ---------------------------------------------------------------------------
__global__ __launch_bounds__(256) void project_scatter(const float* __restrict__ pts,
                                                       const float* __restrict__ Rm,
                                                       const float* __restrict__ Tv,
                                                       const float* __restrict__ focal,
                                                       float* __restrict__ out) {
    const int gt = blockIdx.x * 256 + threadIdx.x;   // 0..131071

    // ---- sentinel fill: out[:] = -1 (coalesced float4; B only overwrites
    // selected slots).
    if (gt < OUTN / 4) {
        reinterpret_cast<float4*>(out)[gt] = make_float4(-1.f, -1.f, -1.f, -1.f);
    }

    const int t = gt >> 3;                           // point id 0..16383
    const int sub = gt & 7;
    const int row = sub >> 1;                        // bbox row 0..3
    const int ch = (sub & 1) << 1;                   // bbox col pair: 0 or 2
    const int b = t >> 13;
    const int n = t & (NPTS - 1);
    const float* p = pts + (size_t)t * 3;
    const float* R = Rm + b * 9;
    const float* T = Tv + b * 3;
    float p0 = p[0], p1 = p[1], p2 = p[2];

    float v0 = __fmaf_rn(p2, R[6], __fmaf_rn(p1, R[3], __fmul_rn(p0, R[0])));
    float v1 = __fmaf_rn(p2, R[7], __fmaf_rn(p1, R[4], __fmul_rn(p0, R[1])));
    float v2 = __fmaf_rn(p2, R[8], __fmaf_rn(p1, R[5], __fmul_rn(p0, R[2])));
    v0 = __fadd_rn(v0, T[0]);
    v1 = __fadd_rn(v1, T[1]);
    float z = __fadd_rn(v2, T[2]);

    float x = -__fdiv_rn(__fmul_rn(focal[0], v0), z);
    float y = -__fdiv_rn(__fmul_rn(focal[1], v1), z);

    if (z > 0.0f) {
        // pixel centers c(i) = 1 - (i+0.5)*0.03125, decreasing in i.
        int ix0 = (int)ceilf(__fmul_rn(1.0f - (x + RADM), 32.0f) - 0.5f);
        int ix1 = (int)floorf(__fmul_rn(1.0f - (x - RADM), 32.0f) - 0.5f);
        int iy0 = (int)ceilf(__fmul_rn(1.0f - (y + RADM), 32.0f) - 0.5f);
        int iy1 = (int)floorf(__fmul_rn(1.0f - (y - RADM), 32.0f) - 0.5f);
        ix0 = max(ix0, 0); ix1 = min(ix1, IMGS - 1);
        iy0 = max(iy0, 0); iy1 = min(iy1, IMGS - 1);

        const int iy = iy0 + row;                   // this lane's bbox row
        if (iy <= iy1) {
            const unsigned long long key =
                ((unsigned long long)__float_as_uint(z) << 32) | (unsigned)n;
            float py = 1.0f - ((float)iy + 0.5f) * 0.03125f;
            float dy = __fsub_rn(py, y);
            float dy2 = __fmul_rn(dy, dy);
#pragma unroll
            for (int c = 0; c < 2; ++c) {
                int ix = ix0 + ch + c;
                bool vx = ix <= ix1;
                float px = 1.0f - ((float)ix + 0.5f) * 0.03125f;
                float dx = __fsub_rn(px, x);
                float d2 = __fadd_rn(__fmul_rn(dx, dx), dy2);
                if (vx && d2 <= RAD2) {             // exact reference predicate
                    int pix = (b << 12) + (iy << 6) + ix;
                    int pos = atomicAdd(&g_cnt[pix], 1);
                    if (pos < CAP)
                        g_plist[(size_t)pix * CAP + pos] =
                            make_ulonglong2(key, (unsigned long long)__float_as_uint(d2));
                }
            }
        }
    }

    // PDL: signal dependent kernel once this thread's writes are issued.
    asm volatile("griddepcontrol.launch_dependents;" ::: "memory");
}

// ---------------------------------------------------------------------------
// Kernel B: one warp per pixel for light pixels, whole-BLOCK cooperation for
// hot pixels (cnt > 64). Output is pre-filled with -1; only winners written.
//   Phase 1 (per warp): cnt<=32 -> 1-key rank; cnt<=64 -> 2-key rank;
//                       cnt>64  -> enqueue to smem hot queue. No early return.
//   Phase 2 (per block): for each queued pixel, 256 threads load all records
//                       to smem (coalesced) and compute ranks via broadcast
//                       smem reads (flat latency, conflict-free).
// Keys unique => rank order = (z, idx) ascending = jax top_k order exactly.
// ---------------------------------------------------------------------------
__global__ __launch_bounds__(256) void select_k(float* __restrict__ out) {
    __shared__ int hotq[8];          // queued pixel ids
    __shared__ int hotc[8];          // their counts
    __shared__ int hotn;
    __shared__ unsigned long long skeys[CAP];
    __shared__ unsigned sd2[CAP];

    const int warp = threadIdx.x >> 5;
    const int lane = threadIdx.x & 31;
    const int pix = blockIdx.x * 8 + warp;          // 0..NPIX-1
    const unsigned long long SENT = ~0ull;
    const unsigned FULL = 0xffffffffu;
    const size_t TSZ = (size_t)NPIX * KSEL;         // 65536
    const size_t o0 = (size_t)pix * KSEL;
    const ulonglong2* __restrict__ list = g_plist + (size_t)pix * CAP;

    if (threadIdx.x == 0) hotn = 0;

    // PDL: block before touching A-produced state.
    asm volatile("griddepcontrol.wait;" ::: "memory");

    // Parallel loads; rec only consumed under lane < cnt.
    int cnt = g_cnt[pix];
    ulonglong2 rec = list[lane];
    cnt = min(cnt, CAP);
    if (lane == 0 && cnt > 0) g_cnt[pix] = 0;       // restore zero-state

    __syncthreads();                                // hotn=0 visible

    // ---------------- Phase 1: per-warp tiers (no early returns) ----------
    if (cnt > 0) {
        if (cnt <= 32) {
            // ---- single-key rank selection (flat latency) ----
            unsigned long long myk = (lane < cnt) ? rec.x : SENT;
            int rank = 0;
            for (int c = 0; c < cnt; ++c) {         // warp-uniform bound
                unsigned long long kc = __shfl_sync(FULL, myk, c);
                rank += (kc < myk) ? 1 : 0;
            }
            if (lane < cnt && rank < KSEL) {
                out[o0 + rank] = (float)(unsigned)myk;                         // idx
                out[TSZ + o0 + rank] = __uint_as_float((unsigned)(myk >> 32)); // z
                out[2 * TSZ + o0 + rank] = __uint_as_float((unsigned)rec.y);   // d2
            }
        } else if (cnt <= 64) {
            // ---- two-key rank selection ----
            unsigned long long k0 = rec.x;          // lane < 32 < cnt: valid
            unsigned long long k1 = SENT;
            unsigned d1bits = 0;
            if (lane + 32 < cnt) {
                ulonglong2 rec2 = list[lane + 32];
                k1 = rec2.x;
                d1bits = (unsigned)rec2.y;
            }
            int r0 = 0, r1 = 0;
#pragma unroll 4
            for (int c = 0; c < 32; ++c) {
                unsigned long long kc = __shfl_sync(FULL, k0, c);
                r0 += (kc < k0) ? 1 : 0;
                r1 += (kc < k1) ? 1 : 0;
            }
            for (int c = 32; c < cnt; ++c) {
                unsigned long long kc = __shfl_sync(FULL, k1, c - 32);
                r0 += (kc < k0) ? 1 : 0;
                r1 += (kc < k1) ? 1 : 0;
            }
            if (r0 < KSEL) {
                out[o0 + r0] = (float)(unsigned)k0;
                out[TSZ + o0 + r0] = __uint_as_float((unsigned)(k0 >> 32));
                out[2 * TSZ + o0 + r0] = __uint_as_float((unsigned)rec.y);
            }
            if (lane + 32 < cnt && r1 < KSEL) {
                out[o0 + r1] = (float)(unsigned)k1;
                out[TSZ + o0 + r1] = __uint_as_float((unsigned)(k1 >> 32));
                out[2 * TSZ + o0 + r1] = __uint_as_float(d1bits);
            }
        } else if (lane == 0) {
            int q = atomicAdd(&hotn, 1);            // smem atomic
            hotq[q] = pix;
            hotc[q] = cnt;
        }
    }

    __syncthreads();

    // ---------------- Phase 2: block-cooperative hot pixels ----------------
    const int nh = hotn;                            // uniform across block
    for (int q = 0; q < nh; ++q) {
        const int hpix = hotq[q];
        const int hcnt = hotc[q];
        const ulonglong2* __restrict__ hl = g_plist + (size_t)hpix * CAP;
        // Coalesced load of all records into smem (one elem per thread).
        for (int i = threadIdx.x; i < hcnt; i += 256) {
            ulonglong2 r2 = hl[i];
            skeys[i] = r2.x;
            sd2[i] = (unsigned)r2.y;
        }
        __syncthreads();
        // Rank via broadcast smem reads: all threads read skeys[j] together.
        const size_t h0 = (size_t)hpix * KSEL;
        for (int i = threadIdx.x; i < hcnt; i += 256) {
            unsigned long long ki = skeys[i];
            int rank = 0;
            for (int j = 0; j < hcnt; ++j)
                rank += (skeys[j] < ki) ? 1 : 0;
            if (rank < KSEL) {                      // hcnt > 64 => ranks 0..7 exist
                out[h0 + rank] = (float)(unsigned)ki;
                out[TSZ + h0 + rank] = __uint_as_float((unsigned)(ki >> 32));
                out[2 * TSZ + h0 + rank] = __uint_as_float(sd2[i]);
            }
        }
        __syncthreads();
    }
}

extern "C" void kernel_launch(void* const* d_in, const int* in_sizes, int n_in,
                              void* d_out, int out_size) {
    const float* pts   = (const float*)d_in[0];  // [2,8192,3]
    const float* Rm    = (const float*)d_in[1];  // [2,3,3]
    const float* Tv    = (const float*)d_in[2];  // [2,3]
    const float* focal = (const float*)d_in[3];  // [2]
    float* out = (float*)d_out;

    project_scatter<<<BATCH * NPTS * 8 / 256, 256>>>(pts, Rm, Tv, focal, out);

    // PDL launch: select_k may begin its prologue while project_scatter runs;
    // it blocks at griddepcontrol.wait until A signals launch_dependents.
    cudaLaunchConfig_t cfg = {};
    cfg.gridDim = dim3(NPIX / 8);
    cfg.blockDim = dim3(256);
    cfg.dynamicSmemBytes = 0;
    cfg.stream = 0;                 // legacy default stream (same as <<<>>>)
    cudaLaunchAttribute at[1];
    at[0].id = cudaLaunchAttributeProgrammaticStreamSerialization;
    at[0].val.programmaticStreamSerializationAllowed = 1;
    cfg.attrs = at;
    cfg.numAttrs = 1;
    cudaLaunchKernelEx(&cfg, select_k, out);
}

// round 14
// speedup vs baseline: 1.6089x; 1.6089x over previous
#include <cuda_runtime.h>
#include <cstdint>

#define BATCH 2
#define NPTS 8192
#define IMGS 64
#define KSEL 8
#define RAD2 0.0025f
#define RADM 0.0501f            // conservative bbox radius
#define NPIX (BATCH * IMGS * IMGS)   // 8192
#define CAP 256                 // per-pixel capacity (hot pixel ~150; +13 sigma)
#define OUTN (3 * NPIX * KSEL)  // 196608 floats

// Static scratch (allocation-free). BSS-zero at load; select_k restores
// g_cnt to zero every launch (graph-replay invariant).
__device__ int g_cnt[NPIX];
__device__ ulonglong2 g_plist[(size_t)NPIX * CAP];   // {key, d2bits} — 32 MB

// ---------------------------------------------------------------------------
// Kernel A: -1-fill the output, then project + scatter. EIGHT lanes per
// point, each owns a 1x2 sub-row of the 4x4 bbox. Ends in
// griddepcontrol.launch_dependents (PDL) so select_k releases early.
// ---------------------------------------------------------------------------
__global__ __launch_bounds__(256) void project_scatter(const float* __restrict__ pts,
                                                       const float* __restrict__ Rm,
                                                       const float* __restrict__ Tv,
                                                       const float* __restrict__ focal,
                                                       float* __restrict__ out) {
    const int gt = blockIdx.x * 256 + threadIdx.x;   // 0..131071

    // ---- sentinel fill: out[:] = -1 (coalesced float4; B only overwrites
    // selected slots).
    if (gt < OUTN / 4) {
        reinterpret_cast<float4*>(out)[gt] = make_float4(-1.f, -1.f, -1.f, -1.f);
    }

    const int t = gt >> 3;                           // point id 0..16383
    const int sub = gt & 7;
    const int row = sub >> 1;                        // bbox row 0..3
    const int ch = (sub & 1) << 1;                   // bbox col pair: 0 or 2
    const int b = t >> 13;
    const int n = t & (NPTS - 1);
    const float* p = pts + (size_t)t * 3;
    const float* R = Rm + b * 9;
    const float* T = Tv + b * 3;
    float p0 = p[0], p1 = p[1], p2 = p[2];

    float v0 = __fmaf_rn(p2, R[6], __fmaf_rn(p1, R[3], __fmul_rn(p0, R[0])));
    float v1 = __fmaf_rn(p2, R[7], __fmaf_rn(p1, R[4], __fmul_rn(p0, R[1])));
    float v2 = __fmaf_rn(p2, R[8], __fmaf_rn(p1, R[5], __fmul_rn(p0, R[2])));
    v0 = __fadd_rn(v0, T[0]);
    v1 = __fadd_rn(v1, T[1]);
    float z = __fadd_rn(v2, T[2]);

    float x = -__fdiv_rn(__fmul_rn(focal[0], v0), z);
    float y = -__fdiv_rn(__fmul_rn(focal[1], v1), z);

    if (z > 0.0f) {
        // pixel centers c(i) = 1 - (i+0.5)*0.03125, decreasing in i.
        int ix0 = (int)ceilf(__fmul_rn(1.0f - (x + RADM), 32.0f) - 0.5f);
        int ix1 = (int)floorf(__fmul_rn(1.0f - (x - RADM), 32.0f) - 0.5f);
        int iy0 = (int)ceilf(__fmul_rn(1.0f - (y + RADM), 32.0f) - 0.5f);
        int iy1 = (int)floorf(__fmul_rn(1.0f - (y - RADM), 32.0f) - 0.5f);
        ix0 = max(ix0, 0); ix1 = min(ix1, IMGS - 1);
        iy0 = max(iy0, 0); iy1 = min(iy1, IMGS - 1);

        const int iy = iy0 + row;                   // this lane's bbox row
        if (iy <= iy1) {
            const unsigned long long key =
                ((unsigned long long)__float_as_uint(z) << 32) | (unsigned)n;
            float py = 1.0f - ((float)iy + 0.5f) * 0.03125f;
            float dy = __fsub_rn(py, y);
            float dy2 = __fmul_rn(dy, dy);
#pragma unroll
            for (int c = 0; c < 2; ++c) {
                int ix = ix0 + ch + c;
                bool vx = ix <= ix1;
                float px = 1.0f - ((float)ix + 0.5f) * 0.03125f;
                float dx = __fsub_rn(px, x);
                float d2 = __fadd_rn(__fmul_rn(dx, dx), dy2);
                if (vx && d2 <= RAD2) {             // exact reference predicate
                    int pix = (b << 12) + (iy << 6) + ix;
                    int pos = atomicAdd(&g_cnt[pix], 1);
                    if (pos < CAP)
                        g_plist[(size_t)pix * CAP + pos] =
                            make_ulonglong2(key, (unsigned long long)__float_as_uint(d2));
                }
            }
        }
    }

    // PDL: signal dependent kernel once this thread's writes are issued.
    asm volatile("griddepcontrol.launch_dependents;" ::: "memory");
}

// ---------------------------------------------------------------------------
// Kernel B: one warp per pixel. Output pre-filled with -1 by A, so B writes
// ONLY winning slots. cnt gates ALL list access: empty warps do one
// broadcast 4B load and retire with zero stores; non-empty warps load only
// written slots (lane < cnt predication) — no cold never-written lines.
//   cnt <= 32  : rank selection, 1 key/lane.
//   cnt <= 64  : rank selection, 2 keys/lane.
//   cnt  > 64  : per-lane sorted top-8; REDUX-min merge; d2 from record.
// Keys unique => (z, idx) ascending = jax top_k order exactly.
// ---------------------------------------------------------------------------
__global__ __launch_bounds__(256) void select_k(float* __restrict__ out) {
    const int warp = threadIdx.x >> 5;
    const int lane = threadIdx.x & 31;
    const int pix = blockIdx.x * 8 + warp;          // 0..NPIX-1
    const unsigned long long SENT = ~0ull;
    const unsigned FULL = 0xffffffffu;
    const size_t TSZ = (size_t)NPIX * KSEL;         // 65536
    const size_t o0 = (size_t)pix * KSEL;
    const ulonglong2* __restrict__ list = g_plist + (size_t)pix * CAP;

    // PDL: block before touching A-produced state.
    asm volatile("griddepcontrol.wait;" ::: "memory");

    int cnt = min(g_cnt[pix], CAP);
    if (cnt == 0) return;                           // out already -1; g_cnt 0

    // Predicated load: only written slots are touched.
    ulonglong2 rec = make_ulonglong2(SENT, 0);
    if (lane < cnt) rec = list[lane];

    if (cnt <= 32) {
        // ---- single-key rank selection (flat latency) ----
        unsigned long long myk = rec.x;             // SENT for lanes >= cnt
        int rank = 0;
        for (int c = 0; c < cnt; ++c) {             // warp-uniform bound
            unsigned long long kc = __shfl_sync(FULL, myk, c);
            rank += (kc < myk) ? 1 : 0;
        }
        if (lane < cnt && rank < KSEL) {
            out[o0 + rank] = (float)(unsigned)myk;                         // idx
            out[TSZ + o0 + rank] = __uint_as_float((unsigned)(myk >> 32)); // z
            out[2 * TSZ + o0 + rank] = __uint_as_float((unsigned)rec.y);   // d2
        }
    } else if (cnt <= 64) {
        // ---- two-key rank selection ----
        unsigned long long k0 = rec.x;              // lane < 32 < cnt: valid
        unsigned long long k1 = SENT;
        unsigned d1bits = 0;
        if (lane + 32 < cnt) {
            ulonglong2 rec2 = list[lane + 32];
            k1 = rec2.x;
            d1bits = (unsigned)rec2.y;
        }
        int r0 = 0, r1 = 0;
#pragma unroll 4
        for (int c = 0; c < 32; ++c) {
            unsigned long long kc = __shfl_sync(FULL, k0, c);
            r0 += (kc < k0) ? 1 : 0;
            r1 += (kc < k1) ? 1 : 0;
        }
        for (int c = 32; c < cnt; ++c) {
            unsigned long long kc = __shfl_sync(FULL, k1, c - 32);
            r0 += (kc < k0) ? 1 : 0;
            r1 += (kc < k1) ? 1 : 0;
        }
        if (r0 < KSEL) {
            out[o0 + r0] = (float)(unsigned)k0;
            out[TSZ + o0 + r0] = __uint_as_float((unsigned)(k0 >> 32));
            out[2 * TSZ + o0 + r0] = __uint_as_float((unsigned)rec.y);
        }
        if (lane + 32 < cnt && r1 < KSEL) {
            out[o0 + r1] = (float)(unsigned)k1;
            out[TSZ + o0 + r1] = __uint_as_float((unsigned)(k1 >> 32));
            out[2 * TSZ + o0 + r1] = __uint_as_float(d1bits);
        }
    } else {
        // ---- per-lane sorted top-8 (keys) + parallel d2 low-reg carry ----
        unsigned long long key[KSEL];
#pragma unroll
        for (int i = 0; i < KSEL; ++i) key[i] = SENT;
        key[0] = rec.x;                             // element `lane` (< cnt)
        for (int j = lane + 32; j < cnt; j += 32) {
            unsigned long long k = list[j].x;
            if (k < key[KSEL - 1]) {
                unsigned long long v = k;
#pragma unroll
                for (int s2 = 0; s2 < KSEL; ++s2) {
                    unsigned long long cur = key[s2];
                    bool lt = v < cur;
                    key[s2] = lt ? v : cur;
                    v = lt ? cur : v;
                }
            }
        }
        // ---- 8 rounds: REDUX-min merge (flat) ----
        unsigned long long mysel = SENT;
#pragma unroll
        for (int r = 0; r < KSEL; ++r) {
            unsigned zhi = (unsigned)(key[0] >> 32);
            unsigned mz = __reduce_min_sync(FULL, zhi);
            unsigned lo = (zhi == mz) ? (unsigned)key[0] : 0xffffffffu;
            unsigned mi = __reduce_min_sync(FULL, lo);
            unsigned long long m = ((unsigned long long)mz << 32) | mi;
            if (key[0] == m) {                      // unique owner pops
#pragma unroll
                for (int s2 = 0; s2 < KSEL - 1; ++s2) key[s2] = key[s2 + 1];
                key[KSEL - 1] = SENT;
            }
            if (lane == r) mysel = m;
        }
        if (lane < KSEL) {                          // cnt > 64 => all valid
            // Winner's d2: its record slot is idx-searchable only via scan;
            // recompute from pixel center and z-packed screen position is
            // impossible without x,y — so re-read the record: winners are
            // within the first cnt slots; find via one gather of list[?].
            // Cheaper: recompute d2 from stored records is not possible;
            // use the d2 stored alongside the winning key by re-scanning the
            // lane-owned slots: winner came from SOME lane's stream, but we
            // know its key only. Instead, gather from g_plist by brute
            // position is O(cnt). Use the reliable path: winner key's d2 via
            // matching ballot during the merge was removed; re-derive by one
            // L2 gather: slot unknown -> fall back to per-lane match scan:
            unsigned myd = 0;
            // Each output lane scans its own strided slots for the key match.
            // Expected hits: winner keys live in exactly one slot; 8 lanes
            // each scan cnt/32 slots of EVERY stride -> cost ~cnt/4 loads.
            for (int j = 0; j < cnt; j += 1) {
                // NOTE: replaced below by broadcast approach; see emit.
                break;
            }
            (void)myd;
            // Simple correct emit: d2 recomputation via match in the 8
            // winner lanes using a warp-cooperative scan:
            // all 32 lanes scan strided slots; if slot key matches any of
            // the 8 winner keys (broadcast), the finder writes d2 directly.
            out[o0 + lane] = (float)(unsigned)mysel;
            out[TSZ + o0 + lane] = __uint_as_float((unsigned)(mysel >> 32));
        }
        // Warp-cooperative d2 emit: broadcast the 8 winner keys, then all
        // lanes scan their strided slots; a lane that owns a winning record
        // writes its d2 to the proper output slot.
        unsigned long long win[KSEL];
#pragma unroll
        for (int r = 0; r < KSEL; ++r)
            win[r] = __shfl_sync(FULL, mysel, r);
        for (int j = lane; j < cnt; j += 32) {
            ulonglong2 r2 = (j == lane) ? rec : list[j];
#pragma unroll
            for (int r = 0; r < KSEL; ++r) {
                if (r2.x == win[r])
                    out[2 * TSZ + o0 + r] = __uint_as_float((unsigned)r2.y);
            }
        }
    }

    if (lane == 0) g_cnt[pix] = 0;   // restore zero-state for next replay
}

extern "C" void kernel_launch(void* const* d_in, const int* in_sizes, int n_in,
                              void* d_out, int out_size) {
    const float* pts   = (const float*)d_in[0];  // [2,8192,3]
    const float* Rm    = (const float*)d_in[1];  // [2,3,3]
    const float* Tv    = (const float*)d_in[2];  // [2,3]
    const float* focal = (const float*)d_in[3];  // [2]
    float* out = (float*)d_out;

    project_scatter<<<BATCH * NPTS * 8 / 256, 256>>>(pts, Rm, Tv, focal, out);

    // PDL launch: select_k may begin its prologue while project_scatter runs;
    // it blocks at griddepcontrol.wait until A signals launch_dependents.
    cudaLaunchConfig_t cfg = {};
    cfg.gridDim = dim3(NPIX / 8);
    cfg.blockDim = dim3(256);
    cfg.dynamicSmemBytes = 0;
    cfg.stream = 0;                 // legacy default stream (same as <<<>>>)
    cudaLaunchAttribute at[1];
    at[0].id = cudaLaunchAttributeProgrammaticStreamSerialization;
    at[0].val.programmaticStreamSerializationAllowed = 1;
    cfg.attrs = at;
    cfg.numAttrs = 1;
    cudaLaunchKernelEx(&cfg, select_k, out);
}